// round 2
// baseline (speedup 1.0000x reference)
#include <cuda_runtime.h>
#include <math.h>

// Problem constants (fixed by reference): B=4, Cin=Cout=256, H=W=64, K=3.
#define BATCH 4
#define CIN   256
#define COUT  256
#define HH    64
#define WWID  64
#define NPIX  (BATCH*HH*WWID)   // 16384

// Tiling
#define TO    128               // Cout tile
#define TP    64                // pixel tile = one output row (r fixed)
#define CC    8                 // Cin channels per K-chunk
#define KCH   (CC*9)            // 72 K-elements per chunk
#define WSTR  (TO+4)            // padded smem stride for W (132 floats)
#define NTHREADS 256

// Per-pixel scale params from the pre-pass.
__device__ float g_f[NPIX];
__device__ int   g_s[NPIX];

// ---------------------------------------------------------------------------
// The reference's _unfold scrambles (Ki,Hout,Kj,Wout) -> (i',j',p') by raw
// linear reshape. For output pixel p' = r*64 + wo:
//   column group j' in {0,1,2}:  q_j = j'*64 + r,  ho_j = q_j/3, kj_j = q_j%3
//   tap(i',j') for dilation s:   X[ho_j + (i'-1)s,  wo + (kj_j-1)s]  (zero pad)
// Scale mean uses the same scramble at dil=1,pad=1:
//   sm = (1/9) sum_{i',j'} scales[ho_j + i' - 1, wo + kj_j - 1]
// ---------------------------------------------------------------------------

__global__ void adaconv_scale_kernel(const float* __restrict__ scales) {
    int pix = blockIdx.x * blockDim.x + threadIdx.x;
    if (pix >= NPIX) return;
    int b  = pix >> 12;
    int r  = (pix >> 6) & 63;
    int wo = pix & 63;
    const float* sb = scales + b * HH * WWID;
    float sum = 0.0f;
#pragma unroll
    for (int jp = 0; jp < 3; jp++) {
        int q  = jp * 64 + r;
        int ho = q / 3;
        int kj = q - 3 * ho;
        int col = wo + kj - 1;
        bool vc = ((unsigned)col < WWID);
#pragma unroll
        for (int ip = 0; ip < 3; ip++) {
            int row = ho + ip - 1;
            if (vc && (unsigned)row < HH)
                sum += sb[row * WWID + col];
        }
    }
    float sm = sum / 9.0f;
    int s = (int)ceilf(sm);
    s = min(3, max(1, s));
    g_f[pix] = sm / (float)s;
    g_s[pix] = s;
}

// ---------------------------------------------------------------------------
// Fused patch-build + implicit GEMM.
//   out[b,o,r,wo] = bias[o] + sum_{c,i,j} W[o,c,i,j] * S[c,i,j]
//   S = separable lerp over the scrambled 3x3 tap grid t[i'][j'] with
//   weights wy(0)=(f,1-f,0), wy(1)=(0,1,0), wy(2)=(0,1-f,f); same for wx.
// Block: 128 outputs x 64 pixels (one output row), 256 threads, 8x4 per thread.
// ---------------------------------------------------------------------------
extern "C" __global__ void __launch_bounds__(NTHREADS)
adaconv_main_kernel(const float* __restrict__ x,
                    const float* __restrict__ weight,
                    const float* __restrict__ bias,
                    float* __restrict__ out) {
    extern __shared__ float smem[];
    float* sW  = smem;                          // KCH * WSTR
    float* sS  = smem + KCH * WSTR;             // KCH * TP  (16B-aligned)
    float* sF  = sS + KCH * TP;                 // TP
    int*   sSc = (int*)(sF + TP);               // TP

    const int tid = threadIdx.x;
    const int bh  = blockIdx.x;                 // b*64 + r
    const int b   = bh >> 6;
    const int r   = bh & 63;
    const int o0  = blockIdx.y * TO;

    // Scramble constants for this output row (depend only on r).
    int hoj[3], kjj[3];
#pragma unroll
    for (int jp = 0; jp < 3; jp++) {
        int q = jp * 64 + r;
        hoj[jp] = q / 3;
        kjj[jp] = q - 3 * hoj[jp];
    }

    if (tid < TP) {
        int pix = bh * WWID + tid;
        sF[tid]  = g_f[pix];
        sSc[tid] = g_s[pix];
    }

    const int og = tid & 15;                    // o = og*8 .. og*8+7
    const int pg = tid >> 4;                    // p = pg*4 .. pg*4+3

    float acc[8][4];
#pragma unroll
    for (int rr = 0; rr < 8; rr++)
#pragma unroll
        for (int qq = 0; qq < 4; qq++) acc[rr][qq] = 0.0f;

    for (int c0 = 0; c0 < CIN; c0 += CC) {
        __syncthreads();

        // ---- stage W chunk, transposed to [k][o], +4 pad ----
        {
            const float* wg = weight + (size_t)o0 * (CIN * 9) + c0 * 9;
            for (int idx = tid; idx < TO * KCH; idx += NTHREADS) {
                int o = idx / KCH;
                int k = idx - o * KCH;          // contiguous in gmem
                sW[k * WSTR + o] = wg[o * (CIN * 9) + k];
            }
        }

        // ---- build S chunk [k=(c,i,j)][p] via scrambled taps + lerp ----
        for (int it = tid; it < CC * TP; it += NTHREADS) {
            int c = it >> 6;
            int p = it & 63;                    // wo
            float f  = sF[p];
            int   sc = sSc[p];
            const float* xc = x + (((size_t)b * CIN + c0 + c) << 12);

            float t[3][3];
#pragma unroll
            for (int jp = 0; jp < 3; jp++) {
                int col = p + (kjj[jp] - 1) * sc;
                bool vc = ((unsigned)col < WWID);
#pragma unroll
                for (int ip = 0; ip < 3; ip++) {
                    int row = hoj[jp] + (ip - 1) * sc;
                    t[ip][jp] = (vc && (unsigned)row < HH) ? xc[row * WWID + col]
                                                           : 0.0f;
                }
            }
            float g = 1.0f - f;
            float u[3][3];
#pragma unroll
            for (int ip = 0; ip < 3; ip++) {
                u[ip][0] = f * t[ip][0] + g * t[ip][1];
                u[ip][1] = t[ip][1];
                u[ip][2] = g * t[ip][1] + f * t[ip][2];
            }
            float* sp = &sS[c * 9 * TP + p];
#pragma unroll
            for (int j = 0; j < 3; j++) {
                sp[(0 * 3 + j) * TP] = f * u[0][j] + g * u[1][j];
                sp[(1 * 3 + j) * TP] = u[1][j];
                sp[(2 * 3 + j) * TP] = g * u[1][j] + f * u[2][j];
            }
        }

        __syncthreads();

        // ---- GEMM over this chunk's 72 K-elements ----
#pragma unroll 8
        for (int k = 0; k < KCH; k++) {
            float4 sv = *(const float4*)&sS[k * TP + (pg << 2)];
            float4 w0 = *(const float4*)&sW[k * WSTR + (og << 3)];
            float4 w1 = *(const float4*)&sW[k * WSTR + (og << 3) + 4];
            float wv[8] = {w0.x, w0.y, w0.z, w0.w, w1.x, w1.y, w1.z, w1.w};
            float pv[4] = {sv.x, sv.y, sv.z, sv.w};
#pragma unroll
            for (int rr = 0; rr < 8; rr++)
#pragma unroll
                for (int qq = 0; qq < 4; qq++)
                    acc[rr][qq] += wv[rr] * pv[qq];
        }
    }

    // ---- epilogue ----
#pragma unroll
    for (int rr = 0; rr < 8; rr++) {
        int o = o0 + (og << 3) + rr;
        float bz = bias[o];
        float4 v;
        v.x = acc[rr][0] + bz;
        v.y = acc[rr][1] + bz;
        v.z = acc[rr][2] + bz;
        v.w = acc[rr][3] + bz;
        size_t off = ((((size_t)b * COUT + o) * HH + r) * WWID) + (pg << 2);
        *(float4*)&out[off] = v;
    }
}

// ---------------------------------------------------------------------------
// Entry point. Inputs identified by element count (robust to ordering):
//   x: 4*256*64*64 = 4194304, scales: 16384, weight: 589824, bias: 256.
// ---------------------------------------------------------------------------
extern "C" void kernel_launch(void* const* d_in, const int* in_sizes, int n_in,
                              void* d_out, int out_size) {
    const float *x = 0, *scales = 0, *weight = 0, *bias = 0;
    for (int i = 0; i < n_in; i++) {
        switch (in_sizes[i]) {
            case 4194304: x      = (const float*)d_in[i]; break;
            case 16384:   scales = (const float*)d_in[i]; break;
            case 589824:  weight = (const float*)d_in[i]; break;
            case 256:     bias   = (const float*)d_in[i]; break;
        }
    }
    float* out = (float*)d_out;

    static const int SMEM_BYTES = (KCH * WSTR + KCH * TP + TP + TP) * 4; // 56960
    cudaFuncSetAttribute(adaconv_main_kernel,
                         cudaFuncAttributeMaxDynamicSharedMemorySize, SMEM_BYTES);

    adaconv_scale_kernel<<<NPIX / NTHREADS, NTHREADS>>>(scales);

    dim3 grid(BATCH * HH, COUT / TO);           // (256, 2)
    adaconv_main_kernel<<<grid, NTHREADS, SMEM_BYTES>>>(x, weight, bias, out);
}

// round 3
// speedup vs baseline: 1.2500x; 1.2500x over previous
#include <cuda_runtime.h>
#include <math.h>

// Problem constants (fixed by reference): B=4, Cin=Cout=256, H=W=64, K=3.
#define BATCH 4
#define CIN   256
#define COUT  256
#define HH    64
#define WWID  64
#define NPIX  (BATCH*HH*WWID)   // 16384

// Tiling
#define TO    128               // Cout tile
#define TP    64                // pixel tile = one output row (r fixed)
#define CC    8                 // Cin channels per K-chunk
#define KCH   (CC*9)            // 72 K-elements per chunk
#define WSTR  (TO+4)            // padded smem stride for W (132 floats)
#define NTHREADS 256

// Per-pixel scale params from the pre-pass.
__device__ float g_f[NPIX];
__device__ int   g_s[NPIX];

// ---------------------------------------------------------------------------
// Reference's _unfold scrambles (Ki,Hout,Kj,Wout) -> (i',j',p') by raw linear
// reshape. For output pixel p' = r*64 + wo:
//   column group j' in {0,1,2}:  q_j = j'*64 + r,  ho_j = q_j/3, kj_j = q_j%3
//   tap(i',j') at dilation s:    X[ho_j + (i'-1)s,  wo + (kj_j-1)s] (zero pad)
// ---------------------------------------------------------------------------

__global__ void adaconv_scale_kernel(const float* __restrict__ scales) {
    int pix = blockIdx.x * blockDim.x + threadIdx.x;
    if (pix >= NPIX) return;
    int b  = pix >> 12;
    int r  = (pix >> 6) & 63;
    int wo = pix & 63;
    const float* sb = scales + b * HH * WWID;
    float sum = 0.0f;
#pragma unroll
    for (int jp = 0; jp < 3; jp++) {
        int q  = jp * 64 + r;
        int ho = q / 3;
        int kj = q - 3 * ho;
        int col = wo + kj - 1;
        bool vc = ((unsigned)col < WWID);
#pragma unroll
        for (int ip = 0; ip < 3; ip++) {
            int row = ho + ip - 1;
            if (vc && (unsigned)row < HH)
                sum += sb[row * WWID + col];
        }
    }
    float sm = sum / 9.0f;
    int s = (int)ceilf(sm);
    s = min(3, max(1, s));
    g_f[pix] = sm / (float)s;
    g_s[pix] = s;
}

// ---------------------------------------------------------------------------
// Fused patch-build + implicit GEMM, conflict-free smem addressing.
// Thread (og,pg) computes o in {o0+og*4..+3} U {o0+64+og*4..+3}, p in pg*4..+3.
// ---------------------------------------------------------------------------
extern "C" __global__ void __launch_bounds__(NTHREADS)
adaconv_main_kernel(const float* __restrict__ x,
                    const float* __restrict__ weight,
                    const float* __restrict__ bias,
                    float* __restrict__ out) {
    extern __shared__ float smem[];
    float* sW  = smem;                          // KCH * WSTR
    float* sS  = smem + KCH * WSTR;             // KCH * TP  (16B-aligned)
    float* sF  = sS + KCH * TP;                 // TP
    int*   sSc = (int*)(sF + TP);               // TP

    const int tid = threadIdx.x;
    const int bh  = blockIdx.x;                 // b*64 + r
    const int b   = bh >> 6;
    const int r   = bh & 63;
    const int o0  = blockIdx.y * TO;

    // Scramble constants for this output row (depend only on r).
    int hoj[3], kjj[3];
#pragma unroll
    for (int jp = 0; jp < 3; jp++) {
        int q = jp * 64 + r;
        hoj[jp] = q / 3;
        kjj[jp] = q - 3 * hoj[jp];
    }

    if (tid < TP) {
        int pix = bh * WWID + tid;
        sF[tid]  = g_f[pix];
        sSc[tid] = g_s[pix];
    }

    const int og = tid & 15;                    // o-group
    const int pg = tid >> 4;                    // p-group: p = pg*4..pg*4+3

    float acc[2][4][4];                         // [half][o-in-4][p]
#pragma unroll
    for (int hf = 0; hf < 2; hf++)
#pragma unroll
        for (int i = 0; i < 4; i++)
#pragma unroll
            for (int q = 0; q < 4; q++) acc[hf][i][q] = 0.0f;

    for (int c0 = 0; c0 < CIN; c0 += CC) {
        __syncthreads();

        // ---- stage W chunk, transposed to [k][o], +4 pad ----
        {
            const float* wg = weight + (size_t)o0 * (CIN * 9) + c0 * 9;
            for (int idx = tid; idx < TO * KCH; idx += NTHREADS) {
                int o = idx / KCH;
                int k = idx - o * KCH;          // contiguous in gmem
                sW[k * WSTR + o] = wg[o * (CIN * 9) + k];
            }
        }

        // ---- build S chunk [k=(c,i,j)][p] via scrambled taps + lerp ----
        for (int it = tid; it < CC * TP; it += NTHREADS) {
            int c = it >> 6;
            int p = it & 63;                    // wo
            float f  = sF[p];
            int   sc = sSc[p];
            const float* xc = x + (((size_t)b * CIN + c0 + c) << 12);

            float t[3][3];
#pragma unroll
            for (int jp = 0; jp < 3; jp++) {
                int col = p + (kjj[jp] - 1) * sc;
                bool vc = ((unsigned)col < WWID);
#pragma unroll
                for (int ip = 0; ip < 3; ip++) {
                    int row = hoj[jp] + (ip - 1) * sc;
                    t[ip][jp] = (vc && (unsigned)row < HH) ? xc[row * WWID + col]
                                                           : 0.0f;
                }
            }
            float g = 1.0f - f;
            float u[3][3];
#pragma unroll
            for (int ip = 0; ip < 3; ip++) {
                u[ip][0] = f * t[ip][0] + g * t[ip][1];
                u[ip][1] = t[ip][1];
                u[ip][2] = g * t[ip][1] + f * t[ip][2];
            }
            float* sp = &sS[c * 9 * TP + p];
#pragma unroll
            for (int j = 0; j < 3; j++) {
                sp[(0 * 3 + j) * TP] = f * u[0][j] + g * u[1][j];
                sp[(1 * 3 + j) * TP] = u[1][j];
                sp[(2 * 3 + j) * TP] = g * u[1][j] + f * u[2][j];
            }
        }

        __syncthreads();

        // ---- GEMM over this chunk's 72 K-elements ----
        // Conflict-free: lanes 0..7 load sW at og*16B consecutive addresses.
#pragma unroll 8
        for (int k = 0; k < KCH; k++) {
            float4 w0 = *(const float4*)&sW[k * WSTR + (og << 2)];
            float4 w1 = *(const float4*)&sW[k * WSTR + 64 + (og << 2)];
            float4 sv = *(const float4*)&sS[k * TP + (pg << 2)];
            float wv0[4] = {w0.x, w0.y, w0.z, w0.w};
            float wv1[4] = {w1.x, w1.y, w1.z, w1.w};
            float pv[4]  = {sv.x, sv.y, sv.z, sv.w};
#pragma unroll
            for (int i = 0; i < 4; i++)
#pragma unroll
                for (int q = 0; q < 4; q++) {
                    acc[0][i][q] += wv0[i] * pv[q];
                    acc[1][i][q] += wv1[i] * pv[q];
                }
        }
    }

    // ---- epilogue ----
#pragma unroll
    for (int hf = 0; hf < 2; hf++)
#pragma unroll
    for (int i = 0; i < 4; i++) {
        int o = o0 + hf * 64 + (og << 2) + i;
        float bz = bias[o];
        float4 v;
        v.x = acc[hf][i][0] + bz;
        v.y = acc[hf][i][1] + bz;
        v.z = acc[hf][i][2] + bz;
        v.w = acc[hf][i][3] + bz;
        size_t off = ((((size_t)b * COUT + o) * HH + r) * WWID) + (pg << 2);
        *(float4*)&out[off] = v;
    }
}

// ---------------------------------------------------------------------------
// Entry point. Inputs identified by element count (robust to ordering):
//   x: 4194304, scales: 16384, weight: 589824, bias: 256.
// ---------------------------------------------------------------------------
extern "C" void kernel_launch(void* const* d_in, const int* in_sizes, int n_in,
                              void* d_out, int out_size) {
    const float *x = 0, *scales = 0, *weight = 0, *bias = 0;
    for (int i = 0; i < n_in; i++) {
        switch (in_sizes[i]) {
            case 4194304: x      = (const float*)d_in[i]; break;
            case 16384:   scales = (const float*)d_in[i]; break;
            case 589824:  weight = (const float*)d_in[i]; break;
            case 256:     bias   = (const float*)d_in[i]; break;
        }
    }
    float* out = (float*)d_out;

    static const int SMEM_BYTES = (KCH * WSTR + KCH * TP + TP + TP) * 4; // 56960
    cudaFuncSetAttribute(adaconv_main_kernel,
                         cudaFuncAttributeMaxDynamicSharedMemorySize, SMEM_BYTES);

    adaconv_scale_kernel<<<NPIX / NTHREADS, NTHREADS>>>(scales);

    dim3 grid(BATCH * HH, COUT / TO);           // (256, 2)
    adaconv_main_kernel<<<grid, NTHREADS, SMEM_BYTES>>>(x, weight, bias, out);
}

// round 4
// speedup vs baseline: 1.5391x; 1.2313x over previous
#include <cuda_runtime.h>
#include <math.h>

// Problem constants (fixed by reference): B=4, Cin=Cout=256, H=W=64, K=3.
#define BATCH 4
#define CIN   256
#define COUT  256
#define HH    64
#define WWID  64
#define NPIX  (BATCH*HH*WWID)   // 16384

// Tiling
#define TO    128               // Cout tile
#define TP    64                // pixel tile = one output row (r fixed)
#define CC    8                 // Cin channels per K-chunk
#define KCH   (CC*9)            // 72 K-elements per chunk
#define WSTR  (TO+4)            // padded smem stride for W (132 floats)
#define NTHREADS 128

// Per-pixel scale params from the pre-pass.
__device__ float g_f[NPIX];
__device__ int   g_s[NPIX];

// ---------------------------------------------------------------------------
// Reference's _unfold scrambles (Ki,Hout,Kj,Wout) -> (i',j',p') by raw linear
// reshape. For output pixel p' = r*64 + wo:
//   column group j' in {0,1,2}:  q_j = j'*64 + r,  ho_j = q_j/3, kj_j = q_j%3
//   tap(i',j') at dilation s:    X[ho_j + (i'-1)s,  wo + (kj_j-1)s] (zero pad)
// ---------------------------------------------------------------------------

__global__ void adaconv_scale_kernel(const float* __restrict__ scales) {
    int pix = blockIdx.x * blockDim.x + threadIdx.x;
    if (pix >= NPIX) return;
    int b  = pix >> 12;
    int r  = (pix >> 6) & 63;
    int wo = pix & 63;
    const float* sb = scales + b * HH * WWID;
    float sum = 0.0f;
#pragma unroll
    for (int jp = 0; jp < 3; jp++) {
        int q  = jp * 64 + r;
        int ho = q / 3;
        int kj = q - 3 * ho;
        int col = wo + kj - 1;
        bool vc = ((unsigned)col < WWID);
#pragma unroll
        for (int ip = 0; ip < 3; ip++) {
            int row = ho + ip - 1;
            if (vc && (unsigned)row < HH)
                sum += sb[row * WWID + col];
        }
    }
    float sm = sum / 9.0f;
    int s = (int)ceilf(sm);
    s = min(3, max(1, s));
    g_f[pix] = sm / (float)s;
    g_s[pix] = s;
}

// ---------------------------------------------------------------------------
// Fused patch-build + implicit GEMM. 128 threads, 8x8 per-thread tile.
// Thread (og,pg): o in {o0+og*4..+3} U {o0+64+og*4..+3}, p in pg*8..pg*8+7.
// ---------------------------------------------------------------------------
extern "C" __global__ void __launch_bounds__(NTHREADS, 4)
adaconv_main_kernel(const float* __restrict__ x,
                    const float* __restrict__ weight,
                    const float* __restrict__ bias,
                    float* __restrict__ out) {
    extern __shared__ float smem[];
    float* sW  = smem;                          // KCH * WSTR
    float* sS  = smem + KCH * WSTR;             // KCH * TP  (16B-aligned)
    float* sF  = sS + KCH * TP;                 // TP
    int*   sSc = (int*)(sF + TP);               // TP

    const int tid = threadIdx.x;
    const int bh  = blockIdx.x;                 // b*64 + r
    const int b   = bh >> 6;
    const int r   = bh & 63;
    const int o0  = blockIdx.y * TO;

    if (tid < TP) {
        int pix = bh * WWID + tid;
        sF[tid]  = g_f[pix];
        sSc[tid] = g_s[pix];
    }
    __syncthreads();

    // ---- per-pixel tap geometry, hoisted out of the channel loop ----
    // This thread builds S for pixel p = tid & 63, channels c = (tid>>6)+2m.
    const int p  = tid & 63;
    const int cb = tid >> 6;                    // 0 or 1
    float f, gg;
    int   toff[3][3];                           // clamped row*64+col
    float tmask[3][3];
    {
        float ff = sF[p];
        int   sc = sSc[p];
        f = ff; gg = 1.0f - ff;
#pragma unroll
        for (int jp = 0; jp < 3; jp++) {
            int q  = jp * 64 + r;
            int ho = q / 3;
            int kj = q - 3 * ho;
            int col = p + (kj - 1) * sc;
            bool vc = ((unsigned)col < WWID);
            int colc = min(max(col, 0), WWID - 1);
#pragma unroll
            for (int ip = 0; ip < 3; ip++) {
                int row = ho + (ip - 1) * sc;
                bool v = vc && ((unsigned)row < HH);
                int rowc = min(max(row, 0), HH - 1);
                toff[ip][jp]  = rowc * WWID + colc;
                tmask[ip][jp] = v ? 1.0f : 0.0f;
            }
        }
    }

    const int og = tid & 15;                    // o-group
    const int pg = tid >> 4;                    // p-group: p = pg*8..pg*8+7

    float acc[8][8];
#pragma unroll
    for (int i = 0; i < 8; i++)
#pragma unroll
        for (int q = 0; q < 8; q++) acc[i][q] = 0.0f;

    // W staging index bookkeeping (no divisions): idx = it*128 + tid,
    // o = idx / 72, k = idx % 72, with 9216/128 = 72 iterations.
    int wo_ = (tid >= 72) ? 1 : 0;
    int wk_ = tid - 72 * wo_;

    const float* wg = weight + (size_t)o0 * (CIN * 9);
    const float* xb = x + ((size_t)b * CIN << 12);

    for (int c0 = 0; c0 < CIN; c0 += CC) {
        __syncthreads();

        // ---- stage W chunk transposed to [k][o] (+4 pad) ----
        {
            int o = wo_, k = wk_;
            const float* wgc = wg + c0 * 9;
#pragma unroll 8
            for (int it = 0; it < 72; it++) {
                sW[k * WSTR + o] = wgc[o * (CIN * 9) + k];
                k += 56; o += 1;
                if (k >= 72) { k -= 72; o += 1; }
            }
        }

        // ---- build S chunk [k=(c,i,j)][p]: 4 channels per thread ----
#pragma unroll
        for (int m = 0; m < 4; m++) {
            int c = cb + 2 * m;
            const float* xc = xb + ((size_t)(c0 + c) << 12);
            float t[3][3];
#pragma unroll
            for (int ip = 0; ip < 3; ip++)
#pragma unroll
                for (int jp = 0; jp < 3; jp++)
                    t[ip][jp] = xc[toff[ip][jp]] * tmask[ip][jp];
            float u[3][3];
#pragma unroll
            for (int ip = 0; ip < 3; ip++) {
                u[ip][0] = f * t[ip][0] + gg * t[ip][1];
                u[ip][1] = t[ip][1];
                u[ip][2] = gg * t[ip][1] + f * t[ip][2];
            }
            float* sp = &sS[c * 9 * TP + p];
#pragma unroll
            for (int j = 0; j < 3; j++) {
                sp[(0 * 3 + j) * TP] = f * u[0][j] + gg * u[1][j];
                sp[(1 * 3 + j) * TP] = u[1][j];
                sp[(2 * 3 + j) * TP] = gg * u[1][j] + f * u[2][j];
            }
        }

        __syncthreads();

        // ---- GEMM over this chunk's 72 K-elements, 8x8 per thread ----
#pragma unroll 4
        for (int k = 0; k < KCH; k++) {
            float4 w0 = *(const float4*)&sW[k * WSTR + (og << 2)];
            float4 w1 = *(const float4*)&sW[k * WSTR + 64 + (og << 2)];
            float4 s0 = *(const float4*)&sS[k * TP + (pg << 3)];
            float4 s1 = *(const float4*)&sS[k * TP + (pg << 3) + 4];
            float wv[8] = {w0.x, w0.y, w0.z, w0.w, w1.x, w1.y, w1.z, w1.w};
            float pv[8] = {s0.x, s0.y, s0.z, s0.w, s1.x, s1.y, s1.z, s1.w};
#pragma unroll
            for (int i = 0; i < 8; i++)
#pragma unroll
                for (int q = 0; q < 8; q++)
                    acc[i][q] += wv[i] * pv[q];
        }
    }

    // ---- epilogue ----
#pragma unroll
    for (int i = 0; i < 8; i++) {
        int o = o0 + ((i < 4) ? 0 : 64) + (og << 2) + (i & 3);
        float bz = bias[o];
        size_t off = ((((size_t)b * COUT + o) * HH + r) * WWID) + (pg << 3);
        float4 v0, v1;
        v0.x = acc[i][0] + bz; v0.y = acc[i][1] + bz;
        v0.z = acc[i][2] + bz; v0.w = acc[i][3] + bz;
        v1.x = acc[i][4] + bz; v1.y = acc[i][5] + bz;
        v1.z = acc[i][6] + bz; v1.w = acc[i][7] + bz;
        *(float4*)&out[off]     = v0;
        *(float4*)&out[off + 4] = v1;
    }
}

// ---------------------------------------------------------------------------
// Entry point. Inputs identified by element count (robust to ordering):
//   x: 4194304, scales: 16384, weight: 589824, bias: 256.
// ---------------------------------------------------------------------------
extern "C" void kernel_launch(void* const* d_in, const int* in_sizes, int n_in,
                              void* d_out, int out_size) {
    const float *x = 0, *scales = 0, *weight = 0, *bias = 0;
    for (int i = 0; i < n_in; i++) {
        switch (in_sizes[i]) {
            case 4194304: x      = (const float*)d_in[i]; break;
            case 16384:   scales = (const float*)d_in[i]; break;
            case 589824:  weight = (const float*)d_in[i]; break;
            case 256:     bias   = (const float*)d_in[i]; break;
        }
    }
    float* out = (float*)d_out;

    static const int SMEM_BYTES = (KCH * WSTR + KCH * TP + TP + TP) * 4; // 56960
    cudaFuncSetAttribute(adaconv_main_kernel,
                         cudaFuncAttributeMaxDynamicSharedMemorySize, SMEM_BYTES);

    adaconv_scale_kernel<<<NPIX / 256, 256>>>(scales);

    dim3 grid(BATCH * HH, COUT / TO);           // (256, 2)
    adaconv_main_kernel<<<grid, NTHREADS, SMEM_BYTES>>>(x, weight, bias, out);
}

// round 5
// speedup vs baseline: 3.6910x; 2.3982x over previous
#include <cuda_runtime.h>
#include <cuda_bf16.h>
#include <math.h>
#include <stdint.h>

// Problem constants: B=4, Cin=Cout=256, H=W=64, K=3.
#define BATCH 4
#define CIN   256
#define COUT  256
#define HH    64
#define WWID  64
#define NPIX  (BATCH*HH*WWID)   // 16384
#define KTOT  (CIN*9)           // 2304

// Chunking: 16 channels -> 144 k -> 9 k16 steps per chunk, 16 chunks.
#define CCH    16
#define KPC    144
#define NSTEP  9
#define NCHUNK 16
#define NGS    (NCHUNK*NSTEP)   // 144 global k16-steps

#define NTHREADS 128

// smem layout in u32 words
#define A_WORDS (NSTEP*8*32*4)          // 9216 per buffer (hi / lo)
#define B_PAD   66                       // per-(s,nt) group stride (u32)
#define B_WORDS (NSTEP*8*B_PAD)          // 4752 per buffer
#define OFF_ALO (A_WORDS)                // 9216
#define OFF_BHI (2*A_WORDS)              // 18432
#define OFF_BLO (2*A_WORDS + B_WORDS)    // 23184
#define OFF_SF  (2*A_WORDS + 2*B_WORDS)  // 27936
#define OFF_SSC (OFF_SF + 64)            // 28000
#define SMEM_WORDS (OFF_SSC + 64)        // 28064
#define SMEM_BYTES (SMEM_WORDS*4)        // 112256

// Per-pixel scale params.
__device__ float g_f[NPIX];
__device__ int   g_s[NPIX];

// W pre-split into bf16 hi/lo, fragment-ordered:
// layout [gs(144)][half(2)][mt(8)][lane(32)][reg(4)] u32 (bf16x2).
#define WFRAG (NGS*2*8*32*4)            // 294912
__device__ uint32_t g_whi[WFRAG];
__device__ uint32_t g_wlo[WFRAG];

__device__ __forceinline__ unsigned short bf16b(float x) {
    __nv_bfloat16 h = __float2bfloat16(x);
    return *reinterpret_cast<unsigned short*>(&h);
}
__device__ __forceinline__ float bf16f(unsigned short b) {
    __nv_bfloat16 h = *reinterpret_cast<__nv_bfloat16*>(&b);
    return __bfloat162float(h);
}

__device__ __forceinline__ void mma_bf16(float* c, const uint32_t* a, const uint32_t* b) {
    asm volatile(
        "mma.sync.aligned.m16n8k16.row.col.f32.bf16.bf16.f32 "
        "{%0,%1,%2,%3}, {%4,%5,%6,%7}, {%8,%9}, {%0,%1,%2,%3};\n"
        : "+f"(c[0]), "+f"(c[1]), "+f"(c[2]), "+f"(c[3])
        : "r"(a[0]), "r"(a[1]), "r"(a[2]), "r"(a[3]), "r"(b[0]), "r"(b[1]));
}

// ---------------------------------------------------------------------------
// Kernel 0: split W into bf16 hi/lo, packed in m16n8k16 A-fragment order.
//  A-frag (row.col): reg i: row = l/4 + (i&1)*8, k16 = (l&3)*2 + (i>>1)*8 (+1 in hi half)
// ---------------------------------------------------------------------------
__global__ void adaconv_prep_w(const float* __restrict__ w) {
    int t = blockIdx.x * 256 + threadIdx.x;
    if (t >= WFRAG) return;
    int i    = t & 3;
    int l    = (t >> 2) & 31;
    int mt   = (t >> 7) & 7;
    int half = (t >> 10) & 1;
    int gs   = t >> 11;
    int o = half * 128 + mt * 16 + (l >> 2) + (i & 1) * 8;
    int k = gs * 16 + (l & 3) * 2 + (i >> 1) * 8;
    float v0 = w[(size_t)o * KTOT + k];
    float v1 = w[(size_t)o * KTOT + k + 1];
    unsigned short h0 = bf16b(v0), h1 = bf16b(v1);
    unsigned short l0 = bf16b(v0 - bf16f(h0)), l1 = bf16b(v1 - bf16f(h1));
    g_whi[t] = (uint32_t)h0 | ((uint32_t)h1 << 16);
    g_wlo[t] = (uint32_t)l0 | ((uint32_t)l1 << 16);
}

// ---------------------------------------------------------------------------
// Kernel 1: per-pixel scale params (scrambled-unfold mean, see prior rounds).
// ---------------------------------------------------------------------------
__global__ void adaconv_scale_kernel(const float* __restrict__ scales) {
    int pix = blockIdx.x * blockDim.x + threadIdx.x;
    if (pix >= NPIX) return;
    int b  = pix >> 12;
    int r  = (pix >> 6) & 63;
    int wo = pix & 63;
    const float* sb = scales + b * HH * WWID;
    float sum = 0.0f;
#pragma unroll
    for (int jp = 0; jp < 3; jp++) {
        int q  = jp * 64 + r;
        int ho = q / 3;
        int kj = q - 3 * ho;
        int col = wo + kj - 1;
        bool vc = ((unsigned)col < WWID);
#pragma unroll
        for (int ip = 0; ip < 3; ip++) {
            int row = ho + ip - 1;
            if (vc && (unsigned)row < HH)
                sum += sb[row * WWID + col];
        }
    }
    float sm = sum / 9.0f;
    int s = (int)ceilf(sm);
    s = min(3, max(1, s));
    g_f[pix] = sm / (float)s;
    g_s[pix] = s;
}

// ---------------------------------------------------------------------------
// Kernel 2: fused patch-build + bf16-split tensor-core GEMM.
// Block: 128 Cout (half) x 64 pixels (one output row). 128 threads, 4 warps.
// Warp w: m16-tiles {2w, 2w+1}; all 8 n8-tiles. 3 mma per tile (hi*hi+hi*lo+lo*hi).
// ---------------------------------------------------------------------------
extern "C" __global__ void __launch_bounds__(NTHREADS)
adaconv_main_kernel(const float* __restrict__ x,
                    const float* __restrict__ bias,
                    float* __restrict__ out) {
    extern __shared__ uint32_t smemu[];
    uint32_t* uAhi = smemu;
    uint32_t* uAlo = smemu + OFF_ALO;
    uint32_t* uBhi = smemu + OFF_BHI;
    uint32_t* uBlo = smemu + OFF_BLO;
    float*    sF   = (float*)(smemu + OFF_SF);
    int*      sSc  = (int*)(smemu + OFF_SSC);
    unsigned short* bhi16 = (unsigned short*)uBhi;
    unsigned short* blo16 = (unsigned short*)uBlo;

    const int tid  = threadIdx.x;
    const int bh   = blockIdx.x;                // b*64 + r
    const int b    = bh >> 6;
    const int r    = bh & 63;
    const int half = blockIdx.y;                // Cout half
    const int o0   = half * 128;

    if (tid < 64) {
        int pix = bh * WWID + tid;
        sF[tid]  = g_f[pix];
        sSc[tid] = g_s[pix];
    }
    __syncthreads();

    // ---- per-pixel tap geometry (this thread builds pixel p, channels cb+2m) ----
    const int p  = tid & 63;
    const int cb = tid >> 6;                    // 0 or 1
    const int nt_b = p >> 3;                    // n-tile of this pixel
    const int lrow8 = (p & 7) << 3;             // (p&7)*4*2 words
    float f, gg;
    int   toff[3][3];
    float tmask[3][3];
    {
        float ff = sF[p];
        int   sc = sSc[p];
        f = ff; gg = 1.0f - ff;
#pragma unroll
        for (int jp = 0; jp < 3; jp++) {
            int q  = jp * 64 + r;
            int ho = q / 3;
            int kj = q - 3 * ho;
            int col = p + (kj - 1) * sc;
            bool vc = ((unsigned)col < WWID);
            int colc = min(max(col, 0), WWID - 1);
#pragma unroll
            for (int ip = 0; ip < 3; ip++) {
                int row = ho + (ip - 1) * sc;
                bool v = vc && ((unsigned)row < HH);
                int rowc = min(max(row, 0), HH - 1);
                toff[ip][jp]  = rowc * WWID + colc;
                tmask[ip][jp] = v ? 1.0f : 0.0f;
            }
        }
    }

    const int w = tid >> 5;                     // warp id (m-tiles 2w, 2w+1)
    const int l = tid & 31;                     // lane

    float acc[2][8][4];
#pragma unroll
    for (int mtl = 0; mtl < 2; mtl++)
#pragma unroll
        for (int nt = 0; nt < 8; nt++)
#pragma unroll
            for (int q = 0; q < 4; q++) acc[mtl][nt][q] = 0.0f;

    const float* xb = x + ((size_t)b * CIN << 12);

    for (int chunk = 0; chunk < NCHUNK; chunk++) {
        __syncthreads();

        // ---- stage W fragments: coalesced uint4 copy, frag order preserved ----
#pragma unroll
        for (int s = 0; s < NSTEP; s++) {
            int seg = ((chunk * NSTEP + s) * 2 + half) * 1024;
            const uint4* srcH = (const uint4*)(g_whi + seg);
            const uint4* srcL = (const uint4*)(g_wlo + seg);
            uint4* dstH = (uint4*)(uAhi + s * 1024);
            uint4* dstL = (uint4*)(uAlo + s * 1024);
            dstH[tid]       = srcH[tid];
            dstH[tid + 128] = srcH[tid + 128];
            dstL[tid]       = srcL[tid];
            dstL[tid + 128] = srcL[tid + 128];
        }

        // ---- build S chunk: 8 channels per thread, write bf16 hi/lo frags ----
#pragma unroll
        for (int m = 0; m < 8; m++) {
            int c = cb + 2 * m;                 // channel within chunk (0..15)
            const float* xc = xb + ((size_t)(chunk * CCH + c) << 12);
            float t[3][3];
#pragma unroll
            for (int ip = 0; ip < 3; ip++)
#pragma unroll
                for (int jp = 0; jp < 3; jp++)
                    t[ip][jp] = xc[toff[ip][jp]] * tmask[ip][jp];
            float u[3][3];
#pragma unroll
            for (int ip = 0; ip < 3; ip++) {
                u[ip][0] = f * t[ip][0] + gg * t[ip][1];
                u[ip][1] = t[ip][1];
                u[ip][2] = gg * t[ip][1] + f * t[ip][2];
            }
            float v[9];
#pragma unroll
            for (int j = 0; j < 3; j++) {
                v[j]     = f * u[0][j] + gg * u[1][j];
                v[3 + j] = u[1][j];
                v[6 + j] = gg * u[1][j] + f * u[2][j];
            }
#pragma unroll
            for (int kk = 0; kk < 9; kk++) {
                int k   = c * 9 + kk;           // 0..143
                int s   = k >> 4;
                int k16 = k & 15;
                int pp  = k16 >> 1;
                int hw  = k16 & 1;
                int word = (s * 8 + nt_b) * B_PAD + lrow8 + ((pp & 3) << 1) + (pp >> 2);
                int idx16 = (word << 1) + hw;
                unsigned short hb = bf16b(v[kk]);
                bhi16[idx16] = hb;
                blo16[idx16] = bf16b(v[kk] - bf16f(hb));
            }
        }

        __syncthreads();

        // ---- tensor GEMM over 9 k16-steps ----
#pragma unroll 3
        for (int s = 0; s < NSTEP; s++) {
            int abase = (s * 8 + w * 2) * 128 + l * 4;
            uint4 ah0 = *(const uint4*)&uAhi[abase];
            uint4 ah1 = *(const uint4*)&uAhi[abase + 128];
            uint4 al0 = *(const uint4*)&uAlo[abase];
            uint4 al1 = *(const uint4*)&uAlo[abase + 128];
            uint32_t ahi0[4] = {ah0.x, ah0.y, ah0.z, ah0.w};
            uint32_t ahi1[4] = {ah1.x, ah1.y, ah1.z, ah1.w};
            uint32_t alo0[4] = {al0.x, al0.y, al0.z, al0.w};
            uint32_t alo1[4] = {al1.x, al1.y, al1.z, al1.w};
#pragma unroll
            for (int nt = 0; nt < 8; nt++) {
                int bword = (s * 8 + nt) * B_PAD + l * 2;
                uint2 bh = *(const uint2*)&uBhi[bword];
                uint2 bl = *(const uint2*)&uBlo[bword];
                uint32_t bhi[2] = {bh.x, bh.y};
                uint32_t blo[2] = {bl.x, bl.y};
                mma_bf16(acc[0][nt], ahi0, bhi);
                mma_bf16(acc[0][nt], ahi0, blo);
                mma_bf16(acc[0][nt], alo0, bhi);
                mma_bf16(acc[1][nt], ahi1, bhi);
                mma_bf16(acc[1][nt], ahi1, blo);
                mma_bf16(acc[1][nt], alo1, bhi);
            }
        }
    }

    // ---- epilogue: C-frag rows o0+w*32+mtl*16+l/4 (+8), cols nt*8+2*(l&3) (+1) ----
#pragma unroll
    for (int mtl = 0; mtl < 2; mtl++) {
        int row0 = o0 + w * 32 + mtl * 16 + (l >> 2);
        int row1 = row0 + 8;
        float bz0 = bias[row0];
        float bz1 = bias[row1];
        size_t base0 = (((size_t)b * COUT + row0) * HH + r) * WWID;
        size_t base1 = (((size_t)b * COUT + row1) * HH + r) * WWID;
#pragma unroll
        for (int nt = 0; nt < 8; nt++) {
            int col = nt * 8 + 2 * (l & 3);
            float2 v0 = {acc[mtl][nt][0] + bz0, acc[mtl][nt][1] + bz0};
            float2 v1 = {acc[mtl][nt][2] + bz1, acc[mtl][nt][3] + bz1};
            *(float2*)&out[base0 + col] = v0;
            *(float2*)&out[base1 + col] = v1;
        }
    }
}

// ---------------------------------------------------------------------------
// Entry point. Inputs by element count: x 4194304, scales 16384,
// weight 589824, bias 256. Output fp32.
// ---------------------------------------------------------------------------
extern "C" void kernel_launch(void* const* d_in, const int* in_sizes, int n_in,
                              void* d_out, int out_size) {
    const float *x = 0, *scales = 0, *weight = 0, *bias = 0;
    for (int i = 0; i < n_in; i++) {
        switch (in_sizes[i]) {
            case 4194304: x      = (const float*)d_in[i]; break;
            case 16384:   scales = (const float*)d_in[i]; break;
            case 589824:  weight = (const float*)d_in[i]; break;
            case 256:     bias   = (const float*)d_in[i]; break;
        }
    }
    float* out = (float*)d_out;

    cudaFuncSetAttribute(adaconv_main_kernel,
                         cudaFuncAttributeMaxDynamicSharedMemorySize, SMEM_BYTES);

    adaconv_prep_w<<<(WFRAG + 255) / 256, 256>>>(weight);
    adaconv_scale_kernel<<<NPIX / 256, 256>>>(scales);

    dim3 grid(BATCH * HH, 2);                   // 512 blocks
    adaconv_main_kernel<<<grid, NTHREADS, SMEM_BYTES>>>(x, bias, out);
}

// round 6
// speedup vs baseline: 3.9281x; 1.0642x over previous
#include <cuda_runtime.h>
#include <cuda_bf16.h>
#include <math.h>
#include <stdint.h>

// Problem constants: B=4, Cin=Cout=256, H=W=64, K=3.
#define BATCH 4
#define CIN   256
#define COUT  256
#define HH    64
#define WWID  64
#define NPIX  (BATCH*HH*WWID)   // 16384
#define KTOT  (CIN*9)           // 2304

// Chunking: 16 channels -> 144 k -> 9 k16 steps per chunk, 16 chunks.
#define CCH    16
#define NSTEP  9
#define NCHUNK 16
#define NGS    (NCHUNK*NSTEP)   // 144 global k16-steps

#define NTHREADS 256

// smem: B tile only, interleaved hi/lo per lane.
// Group (s,nt): 132 u32 (128 payload + 4 pad). 72 groups.
#define GSTR   132
#define B_WORDS (NSTEP*8*GSTR)          // 9504
#define OFF_SF  (B_WORDS)               // 9504
#define OFF_SSC (OFF_SF + 64)
#define SMEM_WORDS (OFF_SSC + 64)       // 9632
#define SMEM_BYTES (SMEM_WORDS*4)       // 38528

// Per-pixel scale params.
__device__ float g_f[NPIX];
__device__ int   g_s[NPIX];

// W pre-split into bf16 hi/lo, fragment-ordered:
// layout [gs(144)][half(2)][mt(8)][lane(32)][reg(4)] u32 (bf16x2).
#define WFRAG (NGS*2*8*32*4)            // 294912
__device__ uint32_t g_whi[WFRAG];
__device__ uint32_t g_wlo[WFRAG];

__device__ __forceinline__ unsigned short bf16b(float x) {
    __nv_bfloat16 h = __float2bfloat16(x);
    return *reinterpret_cast<unsigned short*>(&h);
}
__device__ __forceinline__ float bf16f(unsigned short b) {
    __nv_bfloat16 h = *reinterpret_cast<__nv_bfloat16*>(&b);
    return __bfloat162float(h);
}

__device__ __forceinline__ void mma_bf16(float* c, const uint32_t* a, const uint32_t* b) {
    asm volatile(
        "mma.sync.aligned.m16n8k16.row.col.f32.bf16.bf16.f32 "
        "{%0,%1,%2,%3}, {%4,%5,%6,%7}, {%8,%9}, {%0,%1,%2,%3};\n"
        : "+f"(c[0]), "+f"(c[1]), "+f"(c[2]), "+f"(c[3])
        : "r"(a[0]), "r"(a[1]), "r"(a[2]), "r"(a[3]), "r"(b[0]), "r"(b[1]));
}

// ---------------------------------------------------------------------------
// Kernel 0: split W into bf16 hi/lo, m16n8k16 A-fragment order.
// ---------------------------------------------------------------------------
__global__ void adaconv_prep_w(const float* __restrict__ w) {
    int t = blockIdx.x * 256 + threadIdx.x;
    if (t >= WFRAG) return;
    int i    = t & 3;
    int l    = (t >> 2) & 31;
    int mt   = (t >> 7) & 7;
    int half = (t >> 10) & 1;
    int gs   = t >> 11;
    int o = half * 128 + mt * 16 + (l >> 2) + (i & 1) * 8;
    int k = gs * 16 + (l & 3) * 2 + (i >> 1) * 8;
    float v0 = w[(size_t)o * KTOT + k];
    float v1 = w[(size_t)o * KTOT + k + 1];
    unsigned short h0 = bf16b(v0), h1 = bf16b(v1);
    unsigned short l0 = bf16b(v0 - bf16f(h0)), l1 = bf16b(v1 - bf16f(h1));
    g_whi[t] = (uint32_t)h0 | ((uint32_t)h1 << 16);
    g_wlo[t] = (uint32_t)l0 | ((uint32_t)l1 << 16);
}

// ---------------------------------------------------------------------------
// Kernel 1: per-pixel scale params (scrambled-unfold mean).
// ---------------------------------------------------------------------------
__global__ void adaconv_scale_kernel(const float* __restrict__ scales) {
    int pix = blockIdx.x * blockDim.x + threadIdx.x;
    if (pix >= NPIX) return;
    int b  = pix >> 12;
    int r  = (pix >> 6) & 63;
    int wo = pix & 63;
    const float* sb = scales + b * HH * WWID;
    float sum = 0.0f;
#pragma unroll
    for (int jp = 0; jp < 3; jp++) {
        int q  = jp * 64 + r;
        int ho = q / 3;
        int kj = q - 3 * ho;
        int col = wo + kj - 1;
        bool vc = ((unsigned)col < WWID);
#pragma unroll
        for (int ip = 0; ip < 3; ip++) {
            int row = ho + ip - 1;
            if (vc && (unsigned)row < HH)
                sum += sb[row * WWID + col];
        }
    }
    float sm = sum / 9.0f;
    int s = (int)ceilf(sm);
    s = min(3, max(1, s));
    g_f[pix] = sm / (float)s;
    g_s[pix] = s;
}

// ---------------------------------------------------------------------------
// Kernel 2: fused patch-build + bf16-split tensor GEMM.
// Block: 128 Cout (half) x 64 px (one row). 256 threads, 8 warps, 1 m-tile/warp.
// A fragments read directly from gmem (L2-resident). B built in smem,
// interleaved [b0hi,b1hi,b0lo,b1lo] per lane -> one LDS.128 per (s,nt).
// ---------------------------------------------------------------------------
extern "C" __global__ void __launch_bounds__(NTHREADS, 2)
adaconv_main_kernel(const float* __restrict__ x,
                    const float* __restrict__ bias,
                    float* __restrict__ out) {
    extern __shared__ uint32_t smemu[];
    uint32_t* uB  = smemu;
    float*    sF  = (float*)(smemu + OFF_SF);
    int*      sSc = (int*)(smemu + OFF_SSC);

    const int tid  = threadIdx.x;
    const int bh   = blockIdx.x;                // b*64 + r
    const int b    = bh >> 6;
    const int r    = bh & 63;
    const int half = blockIdx.y;
    const int o0   = half * 128;

    if (tid < 64) {
        int pix = bh * WWID + tid;
        sF[tid]  = g_f[pix];
        sSc[tid] = g_s[pix];
    }
    __syncthreads();

    // ---- per-pixel tap geometry: thread builds pixel p, channel-pairs cg+4m ----
    const int p    = tid & 63;
    const int cg   = tid >> 6;                  // 0..3
    const int nt_b = p >> 3;
    const int prow = (p & 7) << 4;              // n*16 words
    float f, gg;
    int   toff[3][3];
    float tmask[3][3];
    {
        float ff = sF[p];
        int   sc = sSc[p];
        f = ff; gg = 1.0f - ff;
#pragma unroll
        for (int jp = 0; jp < 3; jp++) {
            int q  = jp * 64 + r;
            int ho = q / 3;
            int kj = q - 3 * ho;
            int col = p + (kj - 1) * sc;
            bool vc = ((unsigned)col < WWID);
            int colc = min(max(col, 0), WWID - 1);
#pragma unroll
            for (int ip = 0; ip < 3; ip++) {
                int row = ho + (ip - 1) * sc;
                bool v = vc && ((unsigned)row < HH);
                int rowc = min(max(row, 0), HH - 1);
                toff[ip][jp]  = rowc * WWID + colc;
                tmask[ip][jp] = v ? 1.0f : 0.0f;
            }
        }
    }

    const int w = tid >> 5;                     // warp id = m-tile
    const int l = tid & 31;

    float acc[8][4];
#pragma unroll
    for (int nt = 0; nt < 8; nt++)
#pragma unroll
        for (int q = 0; q < 4; q++) acc[nt][q] = 0.0f;

    const float* xb = x + ((size_t)b * CIN << 12);
    const int aoff = half * 1024 + w * 128 + l * 4;   // within a gs segment

    for (int chunk = 0; chunk < NCHUNK; chunk++) {
        __syncthreads();                        // prior MMA reads done

        // ---- build B chunk: 2 channel-pairs per thread ----
#pragma unroll
        for (int m = 0; m < 2; m++) {
            int cpair = cg + 4 * m;             // 0..7
            float v[18];
#pragma unroll
            for (int cc = 0; cc < 2; cc++) {
                int c = 2 * cpair + cc;
                const float* xc = xb + ((size_t)(chunk * CCH + c) << 12);
                float t[3][3];
#pragma unroll
                for (int ip = 0; ip < 3; ip++)
#pragma unroll
                    for (int jp = 0; jp < 3; jp++)
                        t[ip][jp] = xc[toff[ip][jp]] * tmask[ip][jp];
                float u[3][3];
#pragma unroll
                for (int ip = 0; ip < 3; ip++) {
                    u[ip][0] = f * t[ip][0] + gg * t[ip][1];
                    u[ip][1] = t[ip][1];
                    u[ip][2] = gg * t[ip][1] + f * t[ip][2];
                }
                float* vd = v + cc * 9;
#pragma unroll
                for (int j = 0; j < 3; j++) {
                    vd[j]     = f * u[0][j] + gg * u[1][j];
                    vd[3 + j] = u[1][j];
                    vd[6 + j] = gg * u[1][j] + f * u[2][j];
                }
            }
            // 9 word-pairs (k = 18*cpair + 2j, always even -> aligned)
#pragma unroll
            for (int j = 0; j < 9; j++) {
                int k  = 18 * cpair + 2 * j;
                int s  = k >> 4;
                int pp = (k & 15) >> 1;
                int off = (s * 8 + nt_b) * GSTR + prow + ((pp & 3) << 2) + (pp >> 2);
                float v0 = v[2 * j], v1 = v[2 * j + 1];
                unsigned short h0 = bf16b(v0), h1 = bf16b(v1);
                uB[off]     = (uint32_t)h0 | ((uint32_t)h1 << 16);
                uB[off + 2] = (uint32_t)bf16b(v0 - bf16f(h0))
                            | ((uint32_t)bf16b(v1 - bf16f(h1)) << 16);
            }
        }

        __syncthreads();

        // ---- tensor GEMM over 9 k16-steps; A fragments from gmem (L2) ----
#pragma unroll 3
        for (int s = 0; s < NSTEP; s++) {
            int seg = (chunk * NSTEP + s) * 2048 + aoff;
            uint4 ah = *(const uint4*)(g_whi + seg);
            uint4 al = *(const uint4*)(g_wlo + seg);
            uint32_t ahi[4] = {ah.x, ah.y, ah.z, ah.w};
            uint32_t alo[4] = {al.x, al.y, al.z, al.w};
#pragma unroll
            for (int nt = 0; nt < 8; nt++) {
                uint4 bb = *(const uint4*)&uB[(s * 8 + nt) * GSTR + l * 4];
                uint32_t bhi[2] = {bb.x, bb.y};
                uint32_t blo[2] = {bb.z, bb.w};
                mma_bf16(acc[nt], ahi, bhi);
                mma_bf16(acc[nt], ahi, blo);
                mma_bf16(acc[nt], alo, bhi);
            }
        }
    }

    // ---- epilogue ----
    {
        int row0 = o0 + w * 16 + (l >> 2);
        int row1 = row0 + 8;
        float bz0 = bias[row0];
        float bz1 = bias[row1];
        size_t base0 = (((size_t)b * COUT + row0) * HH + r) * WWID;
        size_t base1 = (((size_t)b * COUT + row1) * HH + r) * WWID;
#pragma unroll
        for (int nt = 0; nt < 8; nt++) {
            int col = nt * 8 + 2 * (l & 3);
            float2 v0 = {acc[nt][0] + bz0, acc[nt][1] + bz0};
            float2 v1 = {acc[nt][2] + bz1, acc[nt][3] + bz1};
            *(float2*)&out[base0 + col] = v0;
            *(float2*)&out[base1 + col] = v1;
        }
    }
}

// ---------------------------------------------------------------------------
// Entry point. Inputs by element count: x 4194304, scales 16384,
// weight 589824, bias 256. Output fp32.
// ---------------------------------------------------------------------------
extern "C" void kernel_launch(void* const* d_in, const int* in_sizes, int n_in,
                              void* d_out, int out_size) {
    const float *x = 0, *scales = 0, *weight = 0, *bias = 0;
    for (int i = 0; i < n_in; i++) {
        switch (in_sizes[i]) {
            case 4194304: x      = (const float*)d_in[i]; break;
            case 16384:   scales = (const float*)d_in[i]; break;
            case 589824:  weight = (const float*)d_in[i]; break;
            case 256:     bias   = (const float*)d_in[i]; break;
        }
    }
    float* out = (float*)d_out;

    cudaFuncSetAttribute(adaconv_main_kernel,
                         cudaFuncAttributeMaxDynamicSharedMemorySize, SMEM_BYTES);

    adaconv_prep_w<<<(WFRAG + 255) / 256, 256>>>(weight);
    adaconv_scale_kernel<<<NPIX / 256, 256>>>(scales);

    dim3 grid(BATCH * HH, 2);                   // 512 blocks
    adaconv_main_kernel<<<grid, NTHREADS, SMEM_BYTES>>>(x, bias, out);
}